// round 2
// baseline (speedup 1.0000x reference)
#include <cuda_runtime.h>
#include <math.h>

#define BATCH 8
#define CIN 64
#define NPIX 1024
#define HID 384
#define NHEADS 3
#define DH 128
#define LAYERS 3
#define KNN 16
#define OUTD 128
#define BN (BATCH*NPIX)           // 8192 total nodes
#define INV_DEG (1.0f/17.0f)
#define ATT_SCALE 0.08838834764831845f   // 1/sqrt(128)

// ---------------- scratch (device globals; no allocation at runtime) ----------------
__device__ float g_h[BN*HID];            // hcur (starts as h0)
__device__ float g_nh[BN*HID];           // normalized h0
__device__ float g_sim[BATCH*NPIX*NPIX]; // cosine sim (33.5 MB)
__device__ int   g_knn[BN*KNN];
__device__ float g_xw[BN*HID];           // gcn xw, later reused for o-proj
__device__ float g_hlocal[BN*HID];
__device__ float g_q[BN*HID];
__device__ float g_k[BN*HID];
__device__ float g_v[BN*HID];
__device__ float g_scores[BATCH*NHEADS*NPIX*NPIX]; // 100 MB
__device__ float g_o[BN*HID];
__device__ float g_tmp[BN*HID];
__device__ float g_mlp1[BN*2*HID];
__device__ float g_mlp2[BN*HID];
__device__ float g_pooled[BATCH*HID];

// ---------------- reductions ----------------
template<int NW>
__device__ __forceinline__ float blk_sum(float v, float* sbuf) {
    #pragma unroll
    for (int o = 16; o; o >>= 1) v += __shfl_xor_sync(0xffffffffu, v, o);
    int tid = threadIdx.x;
    if ((tid & 31) == 0) sbuf[tid >> 5] = v;
    __syncthreads();
    float r = 0.f;
    #pragma unroll
    for (int i = 0; i < NW; i++) r += sbuf[i];
    __syncthreads();
    return r;
}

template<int NW>
__device__ __forceinline__ float blk_max(float v, float* sbuf) {
    #pragma unroll
    for (int o = 16; o; o >>= 1) v = fmaxf(v, __shfl_xor_sync(0xffffffffu, v, o));
    int tid = threadIdx.x;
    if ((tid & 31) == 0) sbuf[tid >> 5] = v;
    __syncthreads();
    float r = -1e30f;
    #pragma unroll
    for (int i = 0; i < NW; i++) r = fmaxf(r, sbuf[i]);
    __syncthreads();
    return r;
}

// ---------------- generic batched SGEMM: C = A @ B(^T) + bias, optional relu ----------------
// batch index z -> z1 = z/zdiv, z2 = z%zdiv; offsets z1*s?1 + z2*s?2 applied per operand.
template<bool TRANSB, bool RELU>
__global__ void __launch_bounds__(256) sgemm(
    const float* __restrict__ A, int lda, long long sA1, long long sA2,
    const float* __restrict__ B, int ldb, long long sB1, long long sB2,
    float* __restrict__ C, int ldc, long long sC1, long long sC2,
    const float* __restrict__ bias, int M, int N, int K, int zdiv)
{
    __shared__ float As[16][68];
    __shared__ float Bs[16][68];
    int z = blockIdx.z;
    int z1 = z / zdiv, z2 = z - z1 * zdiv;
    A += z1 * sA1 + z2 * sA2;
    B += z1 * sB1 + z2 * sB2;
    C += z1 * sC1 + z2 * sC2;
    int m0 = blockIdx.y * 64;
    int n0 = blockIdx.x * 64;
    int tid = threadIdx.x;
    int tx = tid & 15, ty = tid >> 4;
    float acc[4][4] = {};
    for (int k0 = 0; k0 < K; k0 += 16) {
        #pragma unroll
        for (int i = 0; i < 4; i++) {
            int idx = tid + i * 256;
            int r = idx >> 4, c = idx & 15;
            As[c][r] = A[(long long)(m0 + r) * lda + k0 + c];
        }
        if (TRANSB) {
            #pragma unroll
            for (int i = 0; i < 4; i++) {
                int idx = tid + i * 256;
                int c = idx & 15, n = idx >> 4;
                Bs[c][n] = B[(long long)(n0 + n) * ldb + k0 + c];
            }
        } else {
            #pragma unroll
            for (int i = 0; i < 4; i++) {
                int idx = tid + i * 256;
                int c = idx >> 6, n = idx & 63;
                Bs[c][n] = B[(long long)(k0 + c) * ldb + n0 + n];
            }
        }
        __syncthreads();
        #pragma unroll
        for (int kk = 0; kk < 16; kk++) {
            float a[4], b[4];
            #pragma unroll
            for (int i = 0; i < 4; i++) a[i] = As[kk][ty * 4 + i];
            #pragma unroll
            for (int j = 0; j < 4; j++) b[j] = Bs[kk][tx * 4 + j];
            #pragma unroll
            for (int i = 0; i < 4; i++)
                #pragma unroll
                for (int j = 0; j < 4; j++)
                    acc[i][j] += a[i] * b[j];
        }
        __syncthreads();
    }
    #pragma unroll
    for (int i = 0; i < 4; i++) {
        int m = m0 + ty * 4 + i;
        #pragma unroll
        for (int j = 0; j < 4; j++) {
            int n = n0 + tx * 4 + j;
            float v = acc[i][j];
            if (bias) v += bias[n];
            if (RELU) v = fmaxf(v, 0.f);
            C[(long long)m * ldc + n] = v;
        }
    }
}

// ---------------- node encoder: h0[b,n,:] = x[b,:,n] @ W_enc + b_enc ----------------
__global__ void encoder_kernel(const float* __restrict__ x,
                               const float* __restrict__ W,
                               const float* __restrict__ b) {
    int row = blockIdx.x;               // 0..8191
    int bb = row >> 10, n = row & 1023;
    __shared__ float xv[CIN];
    int tid = threadIdx.x;              // 128
    if (tid < CIN) xv[tid] = x[(long long)(bb * CIN + tid) * NPIX + n];
    __syncthreads();
    float a0 = 0.f, a1 = 0.f, a2 = 0.f;
    #pragma unroll 8
    for (int c = 0; c < CIN; c++) {
        float xc = xv[c];
        a0 += xc * W[c * HID + tid];
        a1 += xc * W[c * HID + tid + 128];
        a2 += xc * W[c * HID + tid + 256];
    }
    float* out = g_h + (long long)row * HID;
    out[tid]       = a0 + b[tid];
    out[tid + 128] = a1 + b[tid + 128];
    out[tid + 256] = a2 + b[tid + 256];
}

// ---------------- row L2-normalize h0 -> nh ----------------
__global__ void normalize_kernel() {
    __shared__ float sbuf[4];
    int row = blockIdx.x, tid = threadIdx.x;   // 128 threads
    const float* h = g_h + (long long)row * HID;
    float v0 = h[tid], v1 = h[tid + 128], v2 = h[tid + 256];
    float ss = blk_sum<4>(v0 * v0 + v1 * v1 + v2 * v2, sbuf);
    float rs = rsqrtf(ss);
    float* o = g_nh + (long long)row * HID;
    o[tid] = v0 * rs; o[tid + 128] = v1 * rs; o[tid + 256] = v2 * rs;
}

// ---------------- top-16 per sim row (diag excluded via -2) ----------------
__global__ void topk_kernel() {
    __shared__ float vals[NPIX];
    __shared__ float bv[256];
    __shared__ int bi[256];
    int row = blockIdx.x;               // 0..8191
    int bb = row >> 10, n = row & 1023;
    const float* sim = g_sim + ((long long)bb * NPIX + n) * NPIX;
    int tid = threadIdx.x;              // 256
    for (int i = tid; i < NPIX; i += 256) {
        float v = sim[i];
        if (i == n) v -= 2.0f;
        vals[i] = v;
    }
    __syncthreads();
    for (int it = 0; it < KNN; it++) {
        float best = -1e30f; int bidx = 0;
        for (int i = tid; i < NPIX; i += 256) {
            float v = vals[i];
            if (v > best) { best = v; bidx = i; }
        }
        bv[tid] = best; bi[tid] = bidx;
        __syncthreads();
        for (int s = 128; s; s >>= 1) {
            if (tid < s) {
                float v2 = bv[tid + s]; int i2 = bi[tid + s];
                if (v2 > bv[tid] || (v2 == bv[tid] && i2 < bi[tid])) { bv[tid] = v2; bi[tid] = i2; }
            }
            __syncthreads();
        }
        int m = bi[0];
        if (tid == 0) g_knn[row * KNN + it] = m;
        __syncthreads();
        vals[m] = -1e30f;   // every thread writes same value
        __syncthreads();
    }
}

// ---------------- GCN gather + residual + LN -> g_hlocal ----------------
__global__ void gcn_ln_kernel(const float* __restrict__ ln_s, const float* __restrict__ ln_b) {
    __shared__ float sbuf[4];
    __shared__ int nbr[KNN];
    int row = blockIdx.x;
    int bb = row >> 10;
    int tid = threadIdx.x;              // 128
    if (tid < KNN) nbr[tid] = (bb << 10) + g_knn[row * KNN + tid];
    __syncthreads();
    long long base = (long long)row * HID;
    float t[3];
    #pragma unroll
    for (int j = 0; j < 3; j++) {
        int c = tid + j * 128;
        float v = g_xw[base + c];
        #pragma unroll
        for (int e = 0; e < KNN; e++) v += g_xw[(long long)nbr[e] * HID + c];
        t[j] = g_h[base + c] + v * INV_DEG;
    }
    float mu = blk_sum<4>(t[0] + t[1] + t[2], sbuf) * (1.0f / HID);
    float d0 = t[0] - mu, d1 = t[1] - mu, d2 = t[2] - mu;
    float var = blk_sum<4>(d0 * d0 + d1 * d1 + d2 * d2, sbuf) * (1.0f / HID);
    float rs = rsqrtf(var + 1e-5f);
    g_hlocal[base + tid]       = d0 * rs * ln_s[tid]       + ln_b[tid];
    g_hlocal[base + tid + 128] = d1 * rs * ln_s[tid + 128] + ln_b[tid + 128];
    g_hlocal[base + tid + 256] = d2 * rs * ln_s[tid + 256] + ln_b[tid + 256];
}

// ---------------- out = LN(A + Bv)*s+b  (+ extra, added post-LN, if non-null) ----------------
__global__ void add_ln_kernel(const float* __restrict__ A, const float* __restrict__ Bv,
                              const float* __restrict__ extra,
                              const float* __restrict__ ln_s, const float* __restrict__ ln_b,
                              float* __restrict__ out) {
    __shared__ float sbuf[4];
    long long row = blockIdx.x;
    int tid = threadIdx.x;              // 128
    long long base = row * HID;
    float t[3];
    #pragma unroll
    for (int j = 0; j < 3; j++) { int c = tid + j * 128; t[j] = A[base + c] + Bv[base + c]; }
    float mu = blk_sum<4>(t[0] + t[1] + t[2], sbuf) * (1.0f / HID);
    float d[3];
    #pragma unroll
    for (int j = 0; j < 3; j++) d[j] = t[j] - mu;
    float var = blk_sum<4>(d[0] * d[0] + d[1] * d[1] + d[2] * d[2], sbuf) * (1.0f / HID);
    float rs = rsqrtf(var + 1e-5f);
    #pragma unroll
    for (int j = 0; j < 3; j++) {
        int c = tid + j * 128;
        float y = d[j] * rs * ln_s[c] + ln_b[c];
        if (extra) y += extra[base + c];
        out[base + c] = y;
    }
}

// ---------------- row softmax over 1024 logits (scale applied here) ----------------
__global__ void softmax_kernel() {
    __shared__ float sbuf[8];
    long long row = blockIdx.x;          // B*H*N rows
    float* p = g_scores + row * NPIX;
    int tid = threadIdx.x;               // 256
    float4 v = reinterpret_cast<float4*>(p)[tid];
    v.x *= ATT_SCALE; v.y *= ATT_SCALE; v.z *= ATT_SCALE; v.w *= ATT_SCALE;
    float mx = blk_max<8>(fmaxf(fmaxf(v.x, v.y), fmaxf(v.z, v.w)), sbuf);
    float e0 = expf(v.x - mx), e1 = expf(v.y - mx), e2 = expf(v.z - mx), e3 = expf(v.w - mx);
    float s = blk_sum<8>(e0 + e1 + e2 + e3, sbuf);
    float inv = 1.0f / s;
    float4 o; o.x = e0 * inv; o.y = e1 * inv; o.z = e2 * inv; o.w = e3 * inv;
    reinterpret_cast<float4*>(p)[tid] = o;
}

// ---------------- mean pool over N ----------------
__global__ void pool_kernel() {
    int bb = blockIdx.x, tid = threadIdx.x;   // 384 threads
    const float* base = g_h + (long long)bb * NPIX * HID + tid;
    float s = 0.f;
    for (int n = 0; n < NPIX; n++) s += base[(long long)n * HID];
    g_pooled[bb * HID + tid] = s * (1.0f / NPIX);
}

// ---------------- final head: relu(pooled@W1+b1)@W2+b2 ----------------
__global__ void head_kernel(const float* __restrict__ W1, const float* __restrict__ b1,
                            const float* __restrict__ W2, const float* __restrict__ b2,
                            float* __restrict__ out) {
    __shared__ float p[HID];
    __shared__ float z[HID];
    int bb = blockIdx.x, tid = threadIdx.x;   // 128
    #pragma unroll
    for (int j = 0; j < 3; j++) p[tid + j * 128] = g_pooled[bb * HID + tid + j * 128];
    __syncthreads();
    #pragma unroll
    for (int j = 0; j < 3; j++) {
        int hh = tid + j * 128;
        float a = b1[hh];
        for (int c = 0; c < HID; c++) a += p[c] * W1[c * HID + hh];
        z[hh] = fmaxf(a, 0.f);
    }
    __syncthreads();
    float a = b2[tid];
    for (int c = 0; c < HID; c++) a += z[c] * W2[c * OUTD + tid];
    out[bb * OUTD + tid] = a;
}

// ---------------- launch ----------------
extern "C" void kernel_launch(void* const* d_in, const int* in_sizes, int n_in,
                              void* d_out, int out_size) {
    (void)in_sizes; (void)n_in; (void)out_size;
    const float* x      = (const float*)d_in[0];
    const float* W_enc  = (const float*)d_in[1];
    const float* b_enc  = (const float*)d_in[2];
    const float* gcn_W  = (const float*)d_in[3];
    const float* gcn_b  = (const float*)d_in[4];
    const float* Wq     = (const float*)d_in[5];
    const float* bq     = (const float*)d_in[6];
    const float* Wk     = (const float*)d_in[7];
    const float* bk     = (const float*)d_in[8];
    const float* Wv     = (const float*)d_in[9];
    const float* bv     = (const float*)d_in[10];
    const float* Wo     = (const float*)d_in[11];
    const float* bo     = (const float*)d_in[12];
    const float* lns    = (const float*)d_in[13];
    const float* lnb    = (const float*)d_in[14];
    const float* mW1    = (const float*)d_in[15];
    const float* mb1    = (const float*)d_in[16];
    const float* mW2    = (const float*)d_in[17];
    const float* mb2    = (const float*)d_in[18];
    const float* lin1_W = (const float*)d_in[19];
    const float* lin1_b = (const float*)d_in[20];
    const float* lin2_W = (const float*)d_in[21];
    const float* lin2_b = (const float*)d_in[22];

    float *h, *nh, *simb, *xw, *hlocal, *q, *kk, *v, *scores, *o, *tmp, *mlp1, *mlp2;
    cudaGetSymbolAddress((void**)&h,      g_h);
    cudaGetSymbolAddress((void**)&nh,     g_nh);
    cudaGetSymbolAddress((void**)&simb,   g_sim);
    cudaGetSymbolAddress((void**)&xw,     g_xw);
    cudaGetSymbolAddress((void**)&hlocal, g_hlocal);
    cudaGetSymbolAddress((void**)&q,      g_q);
    cudaGetSymbolAddress((void**)&kk,     g_k);
    cudaGetSymbolAddress((void**)&v,      g_v);
    cudaGetSymbolAddress((void**)&scores, g_scores);
    cudaGetSymbolAddress((void**)&o,      g_o);
    cudaGetSymbolAddress((void**)&tmp,    g_tmp);
    cudaGetSymbolAddress((void**)&mlp1,   g_mlp1);
    cudaGetSymbolAddress((void**)&mlp2,   g_mlp2);

    const long long ROWS = (long long)NPIX * HID;       // per-batch stride in h-space
    const long long SIMS = (long long)NPIX * NPIX;

    // 1) encode + normalize
    encoder_kernel<<<BN, 128>>>(x, W_enc, b_enc);
    normalize_kernel<<<BN, 128>>>();

    // 2) sim = nh @ nh^T per batch
    sgemm<true, false><<<dim3(16, 16, BATCH), 256>>>(
        nh, HID, ROWS, 0,   nh, HID, ROWS, 0,
        simb, NPIX, SIMS, 0, nullptr, NPIX, NPIX, HID, 1);

    // 3) kNN
    topk_kernel<<<BN, 256>>>();

    // 4) layers
    for (int l = 0; l < LAYERS; l++) {
        const float* gw  = gcn_W + (long long)l * HID * HID;
        const float* gb  = gcn_b + (long long)l * HID;
        const float* wq  = Wq + (long long)l * HID * HID;  const float* bq_ = bq + (long long)l * HID;
        const float* wk  = Wk + (long long)l * HID * HID;  const float* bk_ = bk + (long long)l * HID;
        const float* wv  = Wv + (long long)l * HID * HID;  const float* bv_ = bv + (long long)l * HID;
        const float* wo  = Wo + (long long)l * HID * HID;  const float* bo_ = bo + (long long)l * HID;
        const float* w1  = mW1 + (long long)l * HID * 2 * HID; const float* b1_ = mb1 + (long long)l * 2 * HID;
        const float* w2  = mW2 + (long long)l * 2 * HID * HID; const float* b2_ = mb2 + (long long)l * HID;
        const float* s0 = lns + (long long)(l * 3 + 0) * HID; const float* bb0 = lnb + (long long)(l * 3 + 0) * HID;
        const float* s1 = lns + (long long)(l * 3 + 1) * HID; const float* bb1 = lnb + (long long)(l * 3 + 1) * HID;
        const float* s2 = lns + (long long)(l * 3 + 2) * HID; const float* bb2 = lnb + (long long)(l * 3 + 2) * HID;

        // GCN linear + gather + LN
        sgemm<false, false><<<dim3(HID / 64, BN / 64, 1), 256>>>(
            h, HID, 0, 0, gw, HID, 0, 0, xw, HID, 0, 0, gb, BN, HID, HID, 1);
        gcn_ln_kernel<<<BN, 128>>>(s0, bb0);

        // q, k, v
        sgemm<false, false><<<dim3(HID / 64, BN / 64, 1), 256>>>(
            h, HID, 0, 0, wq, HID, 0, 0, q, HID, 0, 0, bq_, BN, HID, HID, 1);
        sgemm<false, false><<<dim3(HID / 64, BN / 64, 1), 256>>>(
            h, HID, 0, 0, wk, HID, 0, 0, kk, HID, 0, 0, bk_, BN, HID, HID, 1);
        sgemm<false, false><<<dim3(HID / 64, BN / 64, 1), 256>>>(
            h, HID, 0, 0, wv, HID, 0, 0, v, HID, 0, 0, bv_, BN, HID, HID, 1);

        // scores[b,h] = Q K^T  (z = b*3 + head)
        sgemm<true, false><<<dim3(16, 16, BATCH * NHEADS), 256>>>(
            q, HID, ROWS, DH, kk, HID, ROWS, DH,
            scores, NPIX, (long long)NHEADS * SIMS, SIMS,
            nullptr, NPIX, NPIX, DH, NHEADS);

        softmax_kernel<<<BATCH * NHEADS * NPIX, 256>>>();

        // O[b,:,h,:] = P V
        sgemm<false, false><<<dim3(DH / 64, NPIX / 64, BATCH * NHEADS), 256>>>(
            scores, NPIX, (long long)NHEADS * SIMS, SIMS,
            v, HID, ROWS, DH,
            o, HID, ROWS, DH,
            nullptr, NPIX, DH, NPIX, NHEADS);

        // out projection (into xw, free now) + attn LN + combine with h_local
        sgemm<false, false><<<dim3(HID / 64, BN / 64, 1), 256>>>(
            o, HID, 0, 0, wo, HID, 0, 0, xw, HID, 0, 0, bo_, BN, HID, HID, 1);
        add_ln_kernel<<<BN, 128>>>(h, xw, hlocal, s1, bb1, tmp);

        // FFN
        sgemm<false, true><<<dim3(2 * HID / 64, BN / 64, 1), 256>>>(
            tmp, HID, 0, 0, w1, 2 * HID, 0, 0, mlp1, 2 * HID, 0, 0, b1_, BN, 2 * HID, HID, 1);
        sgemm<false, false><<<dim3(HID / 64, BN / 64, 1), 256>>>(
            mlp1, 2 * HID, 0, 0, w2, HID, 0, 0, mlp2, HID, 0, 0, b2_, BN, HID, 2 * HID, 1);
        add_ln_kernel<<<BN, 128>>>(tmp, mlp2, nullptr, s2, bb2, h);
    }

    // 5) pool + head
    pool_kernel<<<BATCH, 384>>>();
    head_kernel<<<BATCH, 128>>>(lin1_W, lin1_b, lin2_W, lin2_b, (float*)d_out);
}